// round 3
// baseline (speedup 1.0000x reference)
#include <cuda_runtime.h>
#include <cuda_bf16.h>
#include <cstddef>

#define S_LEN 2048
#define B_DIM 64
#define I_DIM 512
#define H_DIM 512
#define BH (B_DIM * H_DIM)          // 32768
#define GX_COLS 1024                // z gates [0,512), n gates [512,1024)

// Scratch: gx[t][b][g] for g in 0..1023 (maps to weight rows 512+g). 512 MB.
__device__ float g_gx[(size_t)S_LEN * B_DIM * GX_COLS];
// Per-group barrier state (8 groups). Zero-initialized at module load; the
// recurrence performs an even number (2048) of sense flips and resets the
// counter each barrier, so state returns to {0,0} after every launch.
__device__ int g_cnt[8];
__device__ volatile int g_sense[8];

typedef unsigned long long ull;

__device__ __forceinline__ ull fma2(ull a, ull b, ull c) {
    ull d;
    asm("fma.rn.f32x2 %0, %1, %2, %3;" : "=l"(d) : "l"(a), "l"(b), "l"(c));
    return d;
}
__device__ __forceinline__ float sum2(ull u) {
    float lo, hi;
    asm("mov.b64 {%0,%1}, %2;" : "=f"(lo), "=f"(hi) : "l"(u));
    return lo + hi;
}

// ---------------------------------------------------------------------------
// Kernel 1: gx = x @ Wih[512:1536]^T + (bias_ih + bias_hh)[512:1536]
// M=131072 (s*64+b), N=1024, K=512. BM=BN=128, BK=16, 256 threads, 8x8 tile.
// ---------------------------------------------------------------------------
__global__ void __launch_bounds__(256, 1)
gx_gemm(const float* __restrict__ x, const float* __restrict__ wih,
        const float* __restrict__ bih, const float* __restrict__ bhh) {
    __shared__ ull As2[8 * 130];   // [kpair][m], f32x2 elements, padded row 130
    __shared__ ull Bs2[8 * 130];   // [kpair][n]

    const int tid = threadIdx.x;
    const int tx = tid & 15;            // n-quadrant (interleaved: n = n0+tx+16j)
    const int ty = tid >> 4;            // m-quadrant (blocked:     m = m0+ty*8+i)
    const int n0 = blockIdx.x * 128;
    const size_t m0 = (size_t)blockIdx.y * 128;
    const int r = tid >> 1;             // row this thread loads (0..127)
    const int half = tid & 1;           // which 8-float half of BK=16
    const int kp0 = half * 4;

    float bz[8];
#pragma unroll
    for (int j = 0; j < 8; j++) {
        int n = n0 + tx + 16 * j;
        bz[j] = bih[512 + n] + bhh[512 + n];
    }

    ull acc[8][8];
#pragma unroll
    for (int i = 0; i < 8; i++)
#pragma unroll
        for (int j = 0; j < 8; j++) acc[i][j] = 0ull;

    const float* arow = x + (m0 + r) * 512 + half * 8;
    const float* brow = wih + (size_t)(512 + n0 + r) * 512 + half * 8;

    // prefetch tile 0
    ulonglong2 A0 = *(const ulonglong2*)(arow);
    ulonglong2 A1 = *(const ulonglong2*)(arow + 4);
    ulonglong2 B0 = *(const ulonglong2*)(brow);
    ulonglong2 B1 = *(const ulonglong2*)(brow + 4);

    for (int kt = 0; kt < 32; kt++) {
        As2[(kp0 + 0) * 130 + r] = A0.x;
        As2[(kp0 + 1) * 130 + r] = A0.y;
        As2[(kp0 + 2) * 130 + r] = A1.x;
        As2[(kp0 + 3) * 130 + r] = A1.y;
        Bs2[(kp0 + 0) * 130 + r] = B0.x;
        Bs2[(kp0 + 1) * 130 + r] = B0.y;
        Bs2[(kp0 + 2) * 130 + r] = B1.x;
        Bs2[(kp0 + 3) * 130 + r] = B1.y;
        __syncthreads();
        if (kt < 31) {
            int ko = (kt + 1) * 16;
            A0 = *(const ulonglong2*)(arow + ko);
            A1 = *(const ulonglong2*)(arow + ko + 4);
            B0 = *(const ulonglong2*)(brow + ko);
            B1 = *(const ulonglong2*)(brow + ko + 4);
        }
#pragma unroll
        for (int kp = 0; kp < 8; kp++) {
            ull av[8], bv[8];
            const ulonglong2* ap = (const ulonglong2*)&As2[kp * 130 + ty * 8];
#pragma unroll
            for (int i2 = 0; i2 < 4; i2++) {
                ulonglong2 t2 = ap[i2];
                av[i2 * 2] = t2.x;
                av[i2 * 2 + 1] = t2.y;
            }
#pragma unroll
            for (int j = 0; j < 8; j++) bv[j] = Bs2[kp * 130 + tx + 16 * j];
#pragma unroll
            for (int i = 0; i < 8; i++)
#pragma unroll
                for (int j = 0; j < 8; j++) acc[i][j] = fma2(av[i], bv[j], acc[i][j]);
        }
        __syncthreads();
    }

#pragma unroll
    for (int i = 0; i < 8; i++) {
        float* orow = g_gx + (m0 + ty * 8 + i) * (size_t)GX_COLS + n0 + tx;
#pragma unroll
        for (int j = 0; j < 8; j++) orow[16 * j] = sum2(acc[i][j]) + bz[j];
    }
}

// ---------------------------------------------------------------------------
// Kernel 2: recurrence. 128 CTAs = 8 groups x 16 CTAs. Group g: batches
// 8g..8g+7. CTA c in group: h-dims [c*32, c*32+32). 256 threads:
// thread = (hdg 0..15)x(kp 0..15): owns hd pair {c*32+2hdg, +1}, k range
// [kp*32, kp*32+32), weights in registers. Warp = 2 hdg x 16 kp.
// h staged in SMEM interleaved as h_s4[b][q][kp] (float4, k = (kp*8+q)*4+e).
// ---------------------------------------------------------------------------
__global__ void __launch_bounds__(256, 1)
rec_kernel(const float* __restrict__ h0, const float* __restrict__ whh,
           float* __restrict__ out) {
    __shared__ float4 h_s4[8][8][17];

    const int tid = threadIdx.x;
    const int bx = blockIdx.x;
    const int grp = bx >> 4;
    const int c = bx & 15;
    const int gb = grp * 8;
    const int lane = tid & 31;
    const int wid = tid >> 5;
    const int kp = lane & 15;
    const int h1 = lane >> 4;
    const int hdg = wid * 2 + h1;
    const int hd0 = c * 32 + hdg * 2;
    const bool isres = (kp == 0);

    // Load this thread's weight slice into registers (step-invariant).
    ulonglong2 wz0[8], wz1[8], wn0[8], wn1[8];
    {
        const ulonglong2* pz0 = (const ulonglong2*)(whh + (size_t)(512 + hd0) * 512 + kp * 32);
        const ulonglong2* pz1 = (const ulonglong2*)(whh + (size_t)(513 + hd0) * 512 + kp * 32);
        const ulonglong2* pn0 = (const ulonglong2*)(whh + (size_t)(1024 + hd0) * 512 + kp * 32);
        const ulonglong2* pn1 = (const ulonglong2*)(whh + (size_t)(1025 + hd0) * 512 + kp * 32);
#pragma unroll
        for (int q = 0; q < 8; q++) {
            wz0[q] = pz0[q];
            wz1[q] = pz1[q];
            wn0[q] = pn0[q];
            wn1[q] = pn1[q];
        }
    }

    // Stage h(-1) = h_0 into SMEM.
    {
        int b = tid >> 5, rr = tid & 31;
        const float4* src = (const float4*)(h0 + (size_t)(gb + b) * 512);
#pragma unroll
        for (int j = 0; j < 4; j++) {
            int k4 = j * 32 + rr;
            h_s4[b][k4 & 7][k4 >> 3] = __ldcg(src + k4);
        }
    }
    __syncthreads();

    int sense = 0;

    for (int t = 0; t < S_LEN; t++) {
        // Prefetch gx[t] for this thread's cells (result lanes only);
        // consumed ~2000 cycles later, hides DRAM latency.
        float2 pgz[8], pgn[8];
        if (isres) {
            const float* gxt = g_gx + (size_t)t * B_DIM * GX_COLS;
#pragma unroll
            for (int b = 0; b < 8; b++) {
                pgz[b] = __ldcg((const float2*)(gxt + (size_t)(gb + b) * GX_COLS + hd0));
                pgn[b] = __ldcg((const float2*)(gxt + (size_t)(gb + b) * GX_COLS + 512 + hd0));
            }
        }

#pragma unroll
        for (int b = 0; b < 8; b++) {
            ull az0 = 0, az1 = 0, an0 = 0, an1 = 0;
#pragma unroll
            for (int q = 0; q < 8; q++) {
                ulonglong2 h2 = *(const ulonglong2*)&h_s4[b][q][kp];
                az0 = fma2(wz0[q].x, h2.x, az0);
                az0 = fma2(wz0[q].y, h2.y, az0);
                az1 = fma2(wz1[q].x, h2.x, az1);
                az1 = fma2(wz1[q].y, h2.y, az1);
                an0 = fma2(wn0[q].x, h2.x, an0);
                an0 = fma2(wn0[q].y, h2.y, an0);
                an1 = fma2(wn1[q].x, h2.x, an1);
                an1 = fma2(wn1[q].y, h2.y, an1);
            }
            float rz0 = sum2(az0), rz1 = sum2(az1);
            float rn0 = sum2(an0), rn1 = sum2(an1);
            // Reduce across the 16 kp lanes (partners stay within the half-warp).
#pragma unroll
            for (int off = 1; off < 16; off <<= 1) {
                rz0 += __shfl_xor_sync(0xffffffffu, rz0, off);
                rz1 += __shfl_xor_sync(0xffffffffu, rz1, off);
                rn0 += __shfl_xor_sync(0xffffffffu, rn0, off);
                rn1 += __shfl_xor_sync(0xffffffffu, rn1, off);
            }
            if (isres) {
                int k4h = hd0 >> 2;
                float4 ho4 = h_s4[b][k4h & 7][k4h >> 3];
                float ho0 = (hd0 & 2) ? ho4.z : ho4.x;
                float ho1 = (hd0 & 2) ? ho4.w : ho4.y;
                float gz0 = pgz[b].x + rz0, gz1 = pgz[b].y + rz1;
                float gn0 = pgn[b].x + rn0, gn1 = pgn[b].y + rn1;
                float z0 = 1.0f / (1.0f + expf(-gz0));
                float z1 = 1.0f / (1.0f + expf(-gz1));
                float n0v = tanhf(gn0), n1v = tanhf(gn1);
                float2 hv;
                hv.x = ho0 + z0 * (n0v - ho0);
                hv.y = ho1 + z1 * (n1v - ho1);
                float* dst = out + (size_t)t * BH + (size_t)(gb + b) * 512 + hd0;
                *(float2*)dst = hv;
                if (t == S_LEN - 1) {
                    float* dn = out + (size_t)S_LEN * BH + (size_t)(gb + b) * 512 + hd0;
                    *(float2*)dn = hv;
                }
            }
        }

        // Group barrier: h[t] writes must be visible before anyone reads them.
        __threadfence();
        __syncthreads();
        sense ^= 1;
        if (tid == 0) {
            if (atomicAdd(&g_cnt[grp], 1) == 15) {
                g_cnt[grp] = 0;
                __threadfence();
                g_sense[grp] = sense;
            } else {
                while (g_sense[grp] != sense) __nanosleep(32);
            }
        }
        __syncthreads();

        // Restage h[t] from out (L2) into interleaved SMEM layout.
        {
            int b = tid >> 5, rr = tid & 31;
            const float4* src = (const float4*)(out + (size_t)t * BH + (size_t)(gb + b) * 512);
#pragma unroll
            for (int j = 0; j < 4; j++) {
                int k4 = j * 32 + rr;
                h_s4[b][k4 & 7][k4 >> 3] = __ldcg(src + k4);
            }
        }
        __syncthreads();
    }
}

extern "C" void kernel_launch(void* const* d_in, const int* in_sizes, int n_in,
                              void* d_out, int out_size) {
    const float* x   = (const float*)d_in[0];  // (S, B, I)
    const float* h0  = (const float*)d_in[1];  // (1, B, H)
    const float* wih = (const float*)d_in[2];  // (3H, I)
    const float* whh = (const float*)d_in[3];  // (3H, H)
    const float* bih = (const float*)d_in[4];  // (3H,)
    const float* bhh = (const float*)d_in[5];  // (3H,)
    float* out = (float*)d_out;                // (1,S,B,H) then (1,B,H)

    dim3 ggrid(8, 1024);                       // N-tiles x M-tiles
    gx_gemm<<<ggrid, 256>>>(x, wih, bih, bhh);
    rec_kernel<<<128, 256>>>(h0, whh, out);
}